// round 7
// baseline (speedup 1.0000x reference)
#include <cuda_runtime.h>
#include <cuda_bf16.h>

// Warp-per-row: 32 threads = 2 item-slots x 16 lanes. No smem, no block sync.
// 128-thread CTAs process 4 independent rows.

__global__ __launch_bounds__(128)
void svdpp_kernel(const int* __restrict__ user_ids,
                  const int* __restrict__ item_ids,
                  const int* __restrict__ offsets,
                  const int* __restrict__ flat_implicit,
                  const float4* __restrict__ user_emb4,
                  const float4* __restrict__ item_emb4,
                  const float4* __restrict__ imp_emb4,
                  const float* __restrict__ user_bias,
                  const float* __restrict__ item_bias,
                  const float* __restrict__ global_bias,
                  float* __restrict__ out,
                  int B, int N) {
    const int wlane = threadIdx.x & 31;
    const int lane  = wlane & 15;         // float4 index within 256B row
    const int slot  = wlane >> 4;         // 0..1
    const int b     = (blockIdx.x << 2) + (threadIdx.x >> 5);
    if (b >= B) return;

    const int start = __ldg(&offsets[b]);
    const int end   = (b + 1 < B) ? __ldg(&offsets[b + 1]) : N;
    const int len   = end - start;

    // Prefetch epilogue operands early — independent of the gather,
    // their latency hides under the main loop.
    const int u  = __ldg(&user_ids[b]);
    const int it = __ldg(&item_ids[b]);
    const float4 u4 = __ldg(&user_emb4[(size_t)u * 16 + lane]);
    const float4 i4 = __ldg(&item_emb4[(size_t)it * 16 + lane]);
    const float  ub = __ldg(&user_bias[u]);
    const float  ib = __ldg(&item_bias[it]);
    const float  gb = __ldg(&global_bias[0]);

    float4 acc = make_float4(0.f, 0.f, 0.f, 0.f);

    int j = start + slot;
    // Main: 4 independent row-gathers in flight per thread (slot stride 2).
    for (; j + 6 < end; j += 8) {
        const int i0 = __ldg(&flat_implicit[j]);
        const int i1 = __ldg(&flat_implicit[j + 2]);
        const int i2 = __ldg(&flat_implicit[j + 4]);
        const int i3 = __ldg(&flat_implicit[j + 6]);
        const float4 a0 = __ldg(&imp_emb4[(size_t)i0 * 16 + lane]);
        const float4 a1 = __ldg(&imp_emb4[(size_t)i1 * 16 + lane]);
        const float4 a2 = __ldg(&imp_emb4[(size_t)i2 * 16 + lane]);
        const float4 a3 = __ldg(&imp_emb4[(size_t)i3 * 16 + lane]);
        acc.x += (a0.x + a1.x) + (a2.x + a3.x);
        acc.y += (a0.y + a1.y) + (a2.y + a3.y);
        acc.z += (a0.z + a1.z) + (a2.z + a3.z);
        acc.w += (a0.w + a1.w) + (a2.w + a3.w);
    }
    // Tail: up to 3 more items for this slot.
    for (; j < end; j += 2) {
        const float4 a = __ldg(&imp_emb4[(size_t)__ldg(&flat_implicit[j]) * 16 + lane]);
        acc.x += a.x; acc.y += a.y; acc.z += a.z; acc.w += a.w;
    }

    // Combine the two slots.
    acc.x += __shfl_xor_sync(0xffffffffu, acc.x, 16);
    acc.y += __shfl_xor_sync(0xffffffffu, acc.y, 16);
    acc.z += __shfl_xor_sync(0xffffffffu, acc.z, 16);
    acc.w += __shfl_xor_sync(0xffffffffu, acc.w, 16);

    const float invnorm = (len > 0) ? rsqrtf((float)len) : 1.0f;

    float dot = (u4.x + acc.x * invnorm) * i4.x
              + (u4.y + acc.y * invnorm) * i4.y
              + (u4.z + acc.z * invnorm) * i4.z
              + (u4.w + acc.w * invnorm) * i4.w;

    // Reduce 16 lanes (both halves hold identical values post-xor).
    #pragma unroll
    for (int off = 8; off > 0; off >>= 1)
        dot += __shfl_down_sync(0xffffffffu, dot, off, 16);

    if (wlane == 0)
        out[b] = dot + ub + ib + gb;
}

extern "C" void kernel_launch(void* const* d_in, const int* in_sizes, int n_in,
                              void* d_out, int out_size) {
    const int*    user_ids      = (const int*)d_in[0];
    const int*    item_ids      = (const int*)d_in[1];
    const int*    offsets       = (const int*)d_in[2];
    const int*    flat_implicit = (const int*)d_in[3];
    const float4* user_emb4     = (const float4*)d_in[4];
    const float4* item_emb4     = (const float4*)d_in[5];
    const float4* imp_emb4      = (const float4*)d_in[6];
    const float*  user_bias     = (const float*)d_in[7];
    const float*  item_bias     = (const float*)d_in[8];
    const float*  global_bias   = (const float*)d_in[9];
    float*        out           = (float*)d_out;

    const int B = in_sizes[0];          // 16384
    const int N = in_sizes[3];          // 819200

    svdpp_kernel<<<(B + 3) / 4, 128>>>(user_ids, item_ids, offsets, flat_implicit,
                                       user_emb4, item_emb4, imp_emb4,
                                       user_bias, item_bias, global_bias,
                                       out, B, N);
}